// round 1
// baseline (speedup 1.0000x reference)
#include <cuda_runtime.h>

// Problem constants (fixed shapes from reference setup_inputs)
#define T_STEPS 4
#define B_BATCH 32            // TB / T = 128/4
#define N_SEQ   1024
#define CIN     512
#define COUT    512
#define M_TOTAL (T_STEPS * B_BATCH * N_SEQ)   // 131072 rows

// Scratch in device globals (no allocations allowed)
__device__ float g_y[(size_t)M_TOTAL * COUT];      // 268 MB GEMM output
#define NPART 256
__device__ float g_psum[NPART * COUT];
__device__ float g_psq [NPART * COUT];
__device__ float g_mean[COUT];
__device__ float g_rstd[COUT];

// ---------------------------------------------------------------------------
// SGEMM: C[m,o] = sum_k A[m,k] * W[o,k]
// A: [M_TOTAL, CIN] row-major, W: [COUT, CIN] row-major, C: [M_TOTAL, COUT]
// Tile 128x128x16, 256 threads, 8x8 per thread.
// ---------------------------------------------------------------------------
#define BM 128
#define BNb 128
#define BK 16
#define TM 8
#define TN 8

__global__ void __launch_bounds__(256)
gemm_k(const float* __restrict__ A, const float* __restrict__ W) {
    __shared__ float As[BK][BM + 4];
    __shared__ float Ws[BK][BNb + 4];

    const int tid = threadIdx.x;
    const int tx = tid & 15;       // 0..15 -> column group
    const int ty = tid >> 4;       // 0..15 -> row group
    const int m0 = blockIdx.y * BM;
    const int n0 = blockIdx.x * BNb;

    float acc[TM][TN];
#pragma unroll
    for (int i = 0; i < TM; i++)
#pragma unroll
        for (int j = 0; j < TN; j++) acc[i][j] = 0.0f;

    for (int k0 = 0; k0 < CIN; k0 += BK) {
        // Load A tile: 128 rows x 16 k = 512 float4 loads
#pragma unroll
        for (int i = 0; i < 2; i++) {
            int idx = tid + i * 256;          // 0..511
            int row = idx >> 2;
            int kv  = idx & 3;
            float4 v = *reinterpret_cast<const float4*>(
                &A[(size_t)(m0 + row) * CIN + k0 + kv * 4]);
            As[kv * 4 + 0][row] = v.x;
            As[kv * 4 + 1][row] = v.y;
            As[kv * 4 + 2][row] = v.z;
            As[kv * 4 + 3][row] = v.w;
        }
        // Load W tile: 128 out-channels x 16 k
#pragma unroll
        for (int i = 0; i < 2; i++) {
            int idx = tid + i * 256;
            int row = idx >> 2;
            int kv  = idx & 3;
            float4 v = *reinterpret_cast<const float4*>(
                &W[(size_t)(n0 + row) * CIN + k0 + kv * 4]);
            Ws[kv * 4 + 0][row] = v.x;
            Ws[kv * 4 + 1][row] = v.y;
            Ws[kv * 4 + 2][row] = v.z;
            Ws[kv * 4 + 3][row] = v.w;
        }
        __syncthreads();

#pragma unroll
        for (int kk = 0; kk < BK; kk++) {
            float a[TM], b[TN];
#pragma unroll
            for (int i = 0; i < TM; i++) a[i] = As[kk][ty * TM + i];
#pragma unroll
            for (int j = 0; j < TN; j++) b[j] = Ws[kk][tx * TN + j];
#pragma unroll
            for (int i = 0; i < TM; i++)
#pragma unroll
                for (int j = 0; j < TN; j++)
                    acc[i][j] = fmaf(a[i], b[j], acc[i][j]);
        }
        __syncthreads();
    }

    // Store 8x8 tile with float4 writes
#pragma unroll
    for (int i = 0; i < TM; i++) {
        const size_t m = (size_t)(m0 + ty * TM + i);
#pragma unroll
        for (int j = 0; j < TN; j += 4) {
            float4 v = make_float4(acc[i][j], acc[i][j + 1], acc[i][j + 2], acc[i][j + 3]);
            *reinterpret_cast<float4*>(&g_y[m * COUT + n0 + tx * TN + j]) = v;
        }
    }
}

// ---------------------------------------------------------------------------
// BN statistics, stage 1: deterministic partial sums per channel.
// Block b handles rows [b*512, (b+1)*512); thread o = channel.
// ---------------------------------------------------------------------------
__global__ void __launch_bounds__(COUT)
stats1_k() {
    const int o = threadIdx.x;
    const int blk = blockIdx.x;
    const int rows = M_TOTAL / NPART;       // 512
    const size_t r0 = (size_t)blk * rows;
    float s = 0.0f, sq = 0.0f;
    for (int r = 0; r < rows; r++) {
        float v = g_y[(r0 + r) * COUT + o];
        s += v;
        sq = fmaf(v, v, sq);
    }
    g_psum[blk * COUT + o] = s;
    g_psq [blk * COUT + o] = sq;
}

// Stage 2: finalize mean / rstd per channel (1 block, 512 threads)
__global__ void __launch_bounds__(COUT)
stats2_k() {
    const int o = threadIdx.x;
    float s = 0.0f, sq = 0.0f;
    for (int i = 0; i < NPART; i++) {
        s  += g_psum[i * COUT + o];
        sq += g_psq [i * COUT + o];
    }
    const float inv_m = 1.0f / (float)M_TOTAL;
    float mean = s * inv_m;
    float var  = sq * inv_m - mean * mean;
    g_mean[o] = mean;
    g_rstd[o] = rsqrtf(var + 1e-5f);
}

// ---------------------------------------------------------------------------
// Fused BN + multistep LIF + output store.
// Thread handles one (b, n, o); iterates t=0..3 sequentially.
// y layout: [(t*B + b)*N + n, o]; out has the same layout ([TB, N, Cout]).
// ---------------------------------------------------------------------------
__global__ void __launch_bounds__(256)
lif_k(const float* __restrict__ gamma, const float* __restrict__ beta,
      float* __restrict__ out) {
    const int idx = blockIdx.x * blockDim.x + threadIdx.x;  // (b*N+n)*COUT + o
    const int total = B_BATCH * N_SEQ * COUT;
    if (idx >= total) return;
    const int o = idx & (COUT - 1);

    const float mean = g_mean[o];
    const float rstd = g_rstd[o];
    const float ga = gamma[o];
    const float be = beta[o];

    const size_t stride = (size_t)B_BATCH * N_SEQ * COUT;   // per-timestep stride
    const size_t base = (size_t)idx;

    float v = 0.0f;
#pragma unroll
    for (int t = 0; t < T_STEPS; t++) {
        const size_t off = base + (size_t)t * stride;
        float raw = g_y[off];
        // BN in reference op order: (y - mean) * rstd, then * gamma + beta
        float xt = (raw - mean) * rstd;
        xt = xt * ga + be;
        // LIF charge (tau=2): v = v + (xt - v)/2  (exact halving)
        float d = xt - v;
        v = v + d * 0.5f;
        // Fire (heaviside, >= 0 at threshold -> 1)
        float sp = (v >= 1.0f) ? 1.0f : 0.0f;
        out[off] = sp;
        // Detached hard reset
        v = v * (1.0f - sp);
    }
}

// ---------------------------------------------------------------------------
extern "C" void kernel_launch(void* const* d_in, const int* in_sizes, int n_in,
                              void* d_out, int out_size) {
    const float* x     = (const float*)d_in[0];  // [TB, N, Cin] = [M_TOTAL, CIN]
    const float* W     = (const float*)d_in[1];  // [COUT, CIN]
    const float* gamma = (const float*)d_in[2];
    const float* beta  = (const float*)d_in[3];
    float* out = (float*)d_out;

    dim3 gemm_grid(COUT / BNb, M_TOTAL / BM);    // (4, 1024)
    gemm_k<<<gemm_grid, 256>>>(x, W);

    stats1_k<<<NPART, COUT>>>();
    stats2_k<<<1, COUT>>>();

    const int total = B_BATCH * N_SEQ * COUT;    // 16.7M threads
    lif_k<<<(total + 255) / 256, 256>>>(gamma, beta, out);
}